// round 3
// baseline (speedup 1.0000x reference)
#include <cuda_runtime.h>

#define DEGREE 20

// Rescaled Clenshaw evaluation of sum_k W_k * P_k(x), then * (1 - x^2).
//
// Standard Clenshaw for Legendre (P_{k+1} = A_k x P_k + B_k P_{k-1},
// A_k=(2k+1)/(k+1), B_k=-k/(k+1)):
//   b_k = c_k + A_k x b_{k+1} + B_{k+1} b_{k+2},  S = b_0.
// Substituting b_k = s_k d_k with s_{k+1} = s_k / A_k (s_0 = 1) makes the
// x-term coefficient exactly 1:
//   d_k = cp_k + x d_{k+1} + g_k d_{k+2},  S = d_0
// where cp_k = c_k * M_k,  M_k = prod_{j<k} A_j = C(2k,k)/2^k,
//       g_k  = -(k+1)^2 / ((2k+1)(2k+3))   (compile-time float immediate
//       after full unroll -> FFMA-imm form, rt_SMSP = 1).
//
// R1 lesson: without a register budget, ptxas capped at 32 regs and spilled
// cp[] to local memory (LDL in the inner loop, fma pipe at 44.7%).
// __launch_bounds__(256, 2) raises the budget to 128 so cp[] + the four
// independent Clenshaw chains stay register-resident.

__device__ __forceinline__ float legendre_eval(float xx, const float* __restrict__ cp) {
    float d1 = 0.0f, d2 = 0.0f;
#pragma unroll
    for (int k = DEGREE; k >= 0; --k) {
        float g = -(float)((k + 1) * (k + 1)) / (float)((2 * k + 1) * (2 * k + 3));
        float u = fmaf(g, d2, cp[k]);   // FFMA-imm (g literal multiplier)
        float d0 = fmaf(xx, d1, u);     // FFMA 3-reg
        d2 = d1;
        d1 = d0;
    }
    float bc = fmaf(-xx, xx, 1.0f);     // 1 - x^2
    return d1 * bc;
}

__global__ __launch_bounds__(256, 2) void legendre_kernel(
    const float* __restrict__ x, const float* __restrict__ W,
    float* __restrict__ out, int n)
{
    // Per-thread scaled coefficients: cp[k] = W[k] * M_k,
    // M_k = prod_{j=1..k} (2j-1)/j (ratios fold to immediates).
    float cp[DEGREE + 1];
    {
        float M = 1.0f;
        cp[0] = __ldg(&W[0]);
#pragma unroll
        for (int k = 1; k <= DEGREE; ++k) {
            M *= (float)(2 * k - 1) / (float)k;
            cp[k] = __ldg(&W[k]) * M;
        }
    }

    const int tid = blockIdx.x * blockDim.x + threadIdx.x;
    const int stride = gridDim.x * blockDim.x;
    const int n4 = n >> 2;

    const float4* __restrict__ x4 = (const float4*)x;
    float4* __restrict__ o4 = (float4*)out;

    // Four independent Clenshaw chains per iteration -> ILP 4 against the
    // 4-cycle FFMA dependence; issue-bound on the fma pipe.
    for (int i = tid; i < n4; i += stride) {
        float4 v = x4[i];
        float4 r;
        r.x = legendre_eval(v.x, cp);
        r.y = legendre_eval(v.y, cp);
        r.z = legendre_eval(v.z, cp);
        r.w = legendre_eval(v.w, cp);
        o4[i] = r;
    }

    // Scalar tail (n % 4 != 0) — not hit for n = 8,000,000 but kept correct.
    for (int i = (n4 << 2) + tid; i < n; i += stride) {
        out[i] = legendre_eval(x[i], cp);
    }
}

extern "C" void kernel_launch(void* const* d_in, const int* in_sizes, int n_in,
                              void* d_out, int out_size) {
    // Identify W by its element count (DEGREE+1); x is the big array.
    const float* x = (const float*)d_in[0];
    const float* W = (const float*)d_in[1];
    if (n_in >= 2 && in_sizes[0] == DEGREE + 1 && in_sizes[1] != DEGREE + 1) {
        x = (const float*)d_in[1];
        W = (const float*)d_in[0];
    }
    float* out = (float*)d_out;
    int n = out_size;

    // 4 blocks/SM target on 148 SMs; ~13 float4 iters/thread amortizes the
    // coefficient prologue and keeps wave imbalance < ~8%.
    legendre_kernel<<<592, 256>>>(x, W, out, n);
}

// round 4
// speedup vs baseline: 1.2113x; 1.2113x over previous
#include <cuda_runtime.h>

#define DEGREE 20

// Rescaled Clenshaw evaluation of sum_k W_k * P_k(x), then * (1 - x^2).
//
//   d_k = cp_k + x d_{k+1} + g_k d_{k+2},  S = d_0
// where cp_k = W_k * M_k,  M_k = prod_{j<k} (2j+1)/(j+1) = C(2k,k)/2^k,
//       g_k  = -(k+1)^2 / ((2k+1)(2k+3))  (compile-time float immediate
//       after full unroll -> FFMA-imm form, rt_SMSP = 1).
//
// R1 lesson: 32-reg cap spilled cp[] (LDL in inner loop).
// R3 lesson: occ==issue==49.8% -> latency-bound; my grid capped occupancy
//            at exactly 4 blocks/SM and each iteration exposed one full
//            DRAM-latency LDG.128 (MLP=1).
// R4 change: software-pipeline the grid-stride loop (prefetch next float4
//            before computing current), budget 64 regs so the extra live
//            float4 doesn't spill.

__device__ __forceinline__ float legendre_eval(float xx, const float* __restrict__ cp) {
    float d1 = 0.0f, d2 = 0.0f;
#pragma unroll
    for (int k = DEGREE; k >= 0; --k) {
        float g = -(float)((k + 1) * (k + 1)) / (float)((2 * k + 1) * (2 * k + 3));
        float u = fmaf(g, d2, cp[k]);   // FFMA-imm (g literal multiplier)
        float d0 = fmaf(xx, d1, u);     // FFMA 3-reg
        d2 = d1;
        d1 = d0;
    }
    float bc = fmaf(-xx, xx, 1.0f);     // 1 - x^2
    return d1 * bc;
}

__device__ __forceinline__ float4 eval4(float4 v, const float* __restrict__ cp) {
    float4 r;
    r.x = legendre_eval(v.x, cp);
    r.y = legendre_eval(v.y, cp);
    r.z = legendre_eval(v.z, cp);
    r.w = legendre_eval(v.w, cp);
    return r;
}

__global__ __launch_bounds__(256, 4) void legendre_kernel(
    const float* __restrict__ x, const float* __restrict__ W,
    float* __restrict__ out, int n)
{
    // Per-thread scaled coefficients: cp[k] = W[k] * M_k.
    // The M_k product is all-constant and folds at compile time, so this is
    // 21 (L1-hot) LDGs + 20 FMUL-imm, amortized over ~14 float4 iterations.
    float cp[DEGREE + 1];
    {
        float M = 1.0f;
        cp[0] = __ldg(&W[0]);
#pragma unroll
        for (int k = 1; k <= DEGREE; ++k) {
            M *= (float)(2 * k - 1) / (float)k;
            cp[k] = __ldg(&W[k]) * M;
        }
    }

    const int tid = blockIdx.x * blockDim.x + threadIdx.x;
    const int stride = gridDim.x * blockDim.x;
    const int n4 = n >> 2;

    const float4* __restrict__ x4 = (const float4*)x;
    float4* __restrict__ o4 = (float4*)out;

    // Software-pipelined grid-stride loop: the next iteration's LDG.128 is
    // issued before the current iteration's 252-cycle Clenshaw chain, so
    // DRAM latency is hidden behind compute instead of exposed per iter.
    int i = tid;
    if (i < n4) {
        float4 v = x4[i];
        for (; i + stride < n4; i += stride) {
            float4 vn = x4[i + stride];   // prefetch (independent of compute)
            o4[i] = eval4(v, cp);
            v = vn;
        }
        o4[i] = eval4(v, cp);
    }

    // Scalar tail (n % 4 != 0) — not hit for n = 8,000,000 but kept correct.
    for (int j = (n4 << 2) + tid; j < n; j += stride) {
        out[j] = legendre_eval(x[j], cp);
    }
}

extern "C" void kernel_launch(void* const* d_in, const int* in_sizes, int n_in,
                              void* d_out, int out_size) {
    // Identify W by its element count (DEGREE+1); x is the big array.
    const float* x = (const float*)d_in[0];
    const float* W = (const float*)d_in[1];
    if (n_in >= 2 && in_sizes[0] == DEGREE + 1 && in_sizes[1] != DEGREE + 1) {
        x = (const float*)d_in[1];
        W = (const float*)d_in[0];
    }
    float* out = (float*)d_out;
    int n = out_size;

    // 592 = exactly 4 resident blocks/SM (one wave at the 64-reg budget);
    // ~14 float4 iters/thread amortizes the coefficient prologue.
    legendre_kernel<<<592, 256>>>(x, W, out, n);
}